// round 13
// baseline (speedup 1.0000x reference)
#include <cuda_runtime.h>
#include <math.h>

#define MAXD 2048
#define TILE 32
#define NTMAX (MAXD / TILE)     // 64
#define ETA 0.005f

// Disjoint partials: slot [p][j] = contribution of row-tile p to column/row j.
// Every slot written exactly once per launch -> no zeroing, no atomics, no fences.
__device__ float g_partM[NTMAX][MAXD];   // 512 KB
__device__ float g_partR[NTMAX][MAXD];   // 512 KB
__device__ float g_m[MAXD];              // m[j]           (pre-scaled by 1/D)
__device__ float g_rm[MAXD];             // rowmean[b] * ETA / D

// ---------------------------------------------------------------------------
// Kernel 1: symmetric strip-pair reduction, cp.async edition.
// Block = 4 tile-pairs: A-strip = x[I-tile, JB..JB+3 tiles] (32x128),
//                       B-strip = x[JB..JB+3 tiles, I-tile] (128x32).
//  * 8 cp.async.cg (16B) per thread: register-independent, ALL in flight
//    (fixes r12 where LDG->STS scoreboard serialized to ~2 outstanding loads)
//  * ONE commit/wait + ONE __syncthreads; zero shared reductions
//  * warp w: pair j = w>>1, pass = w&1; each thread owns one output:
//      pass1 (col l of pair j): partM[I][J*32+l] = sum_u A[u][32j+l]*B[32j+l][u]
//                               partR[I][J*32+l] = sum_u B[32j+l][u]
//      pass2 (row l of pair j): partM[J][I*32+l] = sum_v A[l][32j+v]*B[32j+v][l]
//                               partR[J][I*32+l] = sum_v A[l][32j+v]
//  * diag pair (J==I): pass1 only;  straddle pair (J<I): skipped.
// Shared layout (padded, all access patterns conflict-free):
//   As4[32][33] float4 (row stride 132 words), Bs4[128][9] float4 (stride 36).
// ---------------------------------------------------------------------------
__global__ void __launch_bounds__(256) hebb_tile_kernel(
    const float* __restrict__ x, int D)
{
    const int I  = blockIdx.y;          // row-tile
    const int JB = blockIdx.x << 2;     // first col-tile of this strip
    if (JB + 3 < I) return;             // fully lower-triangle: no-op block

    __shared__ float4 As4[32][33];
    __shared__ float4 Bs4[128][9];

    const int tid = threadIdx.x;
    const int r   = tid >> 3;           // 0..31
    const int c8  = tid & 7;            // 0..7

    // A-strip rows: 4 cp.async (coalesced per 8-lane group).
    {
        const float* arow = x + (size_t)(I * 32 + r) * D + JB * 32;
        #pragma unroll
        for (int jj = 0; jj < 4; jj++) {
            unsigned d = (unsigned)__cvta_generic_to_shared(&As4[r][jj * 8 + c8]);
            const void* s = arow + ((jj * 8 + c8) << 2);
            asm volatile("cp.async.cg.shared.global [%0], [%1], 16;" :: "r"(d), "l"(s));
        }
    }
    // B-strip rows: 4 more cp.async.
    #pragma unroll
    for (int jj = 0; jj < 4; jj++) {
        const int rb = jj * 32 + r;
        unsigned d = (unsigned)__cvta_generic_to_shared(&Bs4[rb][c8]);
        const void* s = x + (size_t)(JB * 32 + rb) * D + I * 32 + (c8 << 2);
        asm volatile("cp.async.cg.shared.global [%0], [%1], 16;" :: "r"(d), "l"(s));
    }
    asm volatile("cp.async.commit_group;");
    asm volatile("cp.async.wait_group 0;");
    __syncthreads();

    const int j     = tid >> 6;         // pair 0..3
    const int which = (tid >> 5) & 1;   // 0 = pass1, 1 = pass2 (warp-uniform)
    const int l     = tid & 31;
    const int J     = JB + j;
    if (J < I) return;                  // straddle pair

    const float* Af = reinterpret_cast<const float*>(As4);
    const float* Bf = reinterpret_cast<const float*>(Bs4);

    if (which == 0) {
        // Column l of pair j.
        float sm = 0.0f, sr = 0.0f;
        const int acol = 32 * j + l;
        const float4* brow = Bs4[32 * j + l];       // LDS.128, conflict-free
        #pragma unroll
        for (int q = 0; q < 8; q++) {
            const float4 b = brow[q];
            const int u = q << 2;
            sm += Af[(u + 0) * 132 + acol] * b.x + Af[(u + 1) * 132 + acol] * b.y
                + Af[(u + 2) * 132 + acol] * b.z + Af[(u + 3) * 132 + acol] * b.w;
            sr += (b.x + b.y) + (b.z + b.w);
        }
        g_partM[I][J * 32 + l] = sm;
        g_partR[I][J * 32 + l] = sr;
    } else if (J > I) {
        // Row l of pair j.
        float sm = 0.0f, sr = 0.0f;
        const float4* arow4 = As4[l];
        #pragma unroll
        for (int q = 0; q < 8; q++) {
            const float4 a = arow4[8 * j + q];      // LDS.128, conflict-free
            const int v = 32 * j + (q << 2);
            sm += a.x * Bf[(v + 0) * 36 + l] + a.y * Bf[(v + 1) * 36 + l]
                + a.z * Bf[(v + 2) * 36 + l] + a.w * Bf[(v + 3) * 36 + l];
            sr += (a.x + a.y) + (a.z + a.w);
        }
        g_partM[J][I * 32 + l] = sm;
        g_partR[J][I * 32 + l] = sr;
    }
}

// ---------------------------------------------------------------------------
// Kernel 2: partials reduction, parallel over columns AND p.
// ---------------------------------------------------------------------------
__global__ void __launch_bounds__(256) hebb_reduce_kernel(int NT, float invD)
{
    __shared__ float sM[8][33];
    __shared__ float sR[8][33];
    const int lane = threadIdx.x & 31;
    const int g    = threadIdx.x >> 5;
    const int j    = blockIdx.x * 32 + lane;

    float sm = 0.0f, sr = 0.0f;
    for (int p = g; p < NT; p += 8) {
        sm += g_partM[p][j];
        sr += g_partR[p][j];
    }
    sM[g][lane] = sm;
    sR[g][lane] = sr;
    __syncthreads();
    if (threadIdx.x < 32) {
        float m = 0.0f, r = 0.0f;
        #pragma unroll
        for (int k = 0; k < 8; k++) { m += sM[k][threadIdx.x]; r += sR[k][threadIdx.x]; }
        const int jj = blockIdx.x * 32 + threadIdx.x;
        g_m[jj]  = m * invD;
        g_rm[jj] = r * (invD * ETA);
    }
}

// ---------------------------------------------------------------------------
// Kernel 3: elementwise outputs. 1024 blocks, rows 2*bid and 2*bid+1,
// all loads front-batched.
// ---------------------------------------------------------------------------
template<int COLS4, bool NK>
__global__ void __launch_bounds__(256) hebb_ew_kernel_s(
    const float* __restrict__ x, const float* __restrict__ kmat,
    float* __restrict__ y, float* __restrict__ nk)
{
    const int tid = threadIdx.x;
    const int c0 = tid, c1 = tid + 256;
    const int row = blockIdx.x * 2;
    const size_t b0 = (size_t)row * COLS4;
    const size_t b1 = b0 + COLS4;

    const float4* m4 = reinterpret_cast<const float4*>(g_m);
    const float4* k0 = reinterpret_cast<const float4*>(kmat) + b0;
    const float4* k1 = reinterpret_cast<const float4*>(kmat) + b1;
    const float4* x0 = reinterpret_cast<const float4*>(x) + b0;
    const float4* x1 = reinterpret_cast<const float4*>(x) + b1;

    float4 ma = m4[c0], mb = m4[c1];
    float4 ka0 = k0[c0], kb0 = k0[c1];
    float4 ka1 = k1[c0], kb1 = k1[c1];
    float4 xa0, xb0, xa1, xb1;
    if (NK) { xa0 = x0[c0]; xb0 = x0[c1]; xa1 = x1[c0]; xb1 = x1[c1]; }
    const float rm0 = g_rm[row];
    const float rm1 = g_rm[row + 1];

    float4* y0 = reinterpret_cast<float4*>(y) + b0;
    float4* y1 = reinterpret_cast<float4*>(y) + b1;

    float4 v;
    v.x = ka0.x * ma.x; v.y = ka0.y * ma.y; v.z = ka0.z * ma.z; v.w = ka0.w * ma.w;
    y0[c0] = v;
    v.x = kb0.x * mb.x; v.y = kb0.y * mb.y; v.z = kb0.z * mb.z; v.w = kb0.w * mb.w;
    y0[c1] = v;
    v.x = ka1.x * ma.x; v.y = ka1.y * ma.y; v.z = ka1.z * ma.z; v.w = ka1.w * ma.w;
    y1[c0] = v;
    v.x = kb1.x * mb.x; v.y = kb1.y * mb.y; v.z = kb1.z * mb.z; v.w = kb1.w * mb.w;
    y1[c1] = v;

    if (NK) {
        float4* n0 = reinterpret_cast<float4*>(nk) + b0;
        float4* n1 = reinterpret_cast<float4*>(nk) + b1;
        v.x = fmaf(rm0, xa0.x, ka0.x); v.y = fmaf(rm0, xa0.y, ka0.y);
        v.z = fmaf(rm0, xa0.z, ka0.z); v.w = fmaf(rm0, xa0.w, ka0.w);
        n0[c0] = v;
        v.x = fmaf(rm0, xb0.x, kb0.x); v.y = fmaf(rm0, xb0.y, kb0.y);
        v.z = fmaf(rm0, xb0.z, kb0.z); v.w = fmaf(rm0, xb0.w, kb0.w);
        n0[c1] = v;
        v.x = fmaf(rm1, xa1.x, ka1.x); v.y = fmaf(rm1, xa1.y, ka1.y);
        v.z = fmaf(rm1, xa1.z, ka1.z); v.w = fmaf(rm1, xa1.w, ka1.w);
        n1[c0] = v;
        v.x = fmaf(rm1, xb1.x, kb1.x); v.y = fmaf(rm1, xb1.y, kb1.y);
        v.z = fmaf(rm1, xb1.z, kb1.z); v.w = fmaf(rm1, xb1.w, kb1.w);
        n1[c1] = v;
    }
}

// Generic fallback (runtime D4).
__global__ void __launch_bounds__(256) hebb_ew_kernel_g(
    const float* __restrict__ x, const float* __restrict__ kmat,
    float* __restrict__ y, float* __restrict__ nk, int D4, int n4, int write_nk)
{
    int idx = blockIdx.x * 256 + threadIdx.x;
    if (idx >= n4) return;
    const int col4 = idx % D4;
    const int row  = idx / D4;
    float4 kv = reinterpret_cast<const float4*>(kmat)[idx];
    float4 mv = reinterpret_cast<const float4*>(g_m)[col4];
    float4 yv;
    yv.x = kv.x * mv.x; yv.y = kv.y * mv.y; yv.z = kv.z * mv.z; yv.w = kv.w * mv.w;
    reinterpret_cast<float4*>(y)[idx] = yv;
    if (write_nk) {
        float rm = g_rm[row];
        float4 xv = reinterpret_cast<const float4*>(x)[idx];
        float4 nv;
        nv.x = fmaf(rm, xv.x, kv.x); nv.y = fmaf(rm, xv.y, kv.y);
        nv.z = fmaf(rm, xv.z, kv.z); nv.w = fmaf(rm, xv.w, kv.w);
        reinterpret_cast<float4*>(nk)[idx] = nv;
    }
}

extern "C" void kernel_launch(void* const* d_in, const int* in_sizes, int n_in,
                              void* d_out, int out_size)
{
    if (n_in < 2 || !d_in || !d_out || !in_sizes) return;

    const float* x    = (const float*)d_in[0];
    const float* kmat = (const float*)d_in[1];
    float* out        = (float*)d_out;

    const int n = in_sizes[0];           // D*D
    int D = 1;
    while (D < MAXD && D * D < n) D++;   // D = 2048 here
    if (D * D != n || (D % 128) != 0) return;

    const int NT = D / TILE;              // 64
    const int write_nk = (out_size >= 2 * n) ? 1 : 0;
    const float invD = 1.0f / (float)D;

    float* y  = out;
    float* nk = out + n;

    dim3 tgrid(NT / 4, NT);               // (16, 64)
    hebb_tile_kernel<<<tgrid, 256>>>(x, D);
    hebb_reduce_kernel<<<D / 32, 256>>>(NT, invD);

    if (D == 2048) {
        if (write_nk)
            hebb_ew_kernel_s<512, true><<<1024, 256>>>(x, kmat, y, nk);
        else
            hebb_ew_kernel_s<512, false><<<1024, 256>>>(x, kmat, y, nk);
    } else {
        const int n4 = n >> 2;
        hebb_ew_kernel_g<<<(n4 + 255) / 256, 256>>>(x, kmat, y, nk, D >> 2, n4, write_nk);
    }
}

// round 15
// speedup vs baseline: 1.0587x; 1.0587x over previous
#include <cuda_runtime.h>

#define MAXD 2048
#define NTMAX 64
#define ETA 0.005f

// Disjoint partials; every slot written exactly once per launch.
__device__ float g_partM[NTMAX][MAXD];   // 512 KB
__device__ float g_partR[NTMAX][MAXD];   // 512 KB
__device__ float g_m[MAXD];              // m[j] pre-scaled by 1/D (written by in-EW reducers)
__device__ float g_rm[MAXD];             // generic-path only
__device__ unsigned int g_flag;          // reducers-done counter (reset by tile kernel)

// ---------------------------------------------------------------------------
// Kernel 1: symmetric strip-pair reduction. 2-tile strips (18 KB smem -> ~8
// blocks/SM). Block (I, JB=2bx): A-strip = x[I, JB..JB+1] (32x64),
// B-strip = x[JB..JB+1, I] (64x32). cp.async loads (4/thread, all in flight).
// 8 warps: combo c = (pair j, pass) x half; halves combined via shared.
//   pass1: partM[I][J*32+l] = sum_u A[u][32j+l]*B[32j+l][u]; partR likewise rowsum of B
//   pass2: partM[J][I*32+l] = sum_v A[l][32j+v]*B[32j+v][l]; partR rowsum of A
// Diag pair: pass1 only. Straddle pair (J<I): computed, not written.
// ---------------------------------------------------------------------------
__global__ void __launch_bounds__(256) hebb_tile_kernel(
    const float* __restrict__ x, int D)
{
    if (blockIdx.x == 0 && blockIdx.y == 0 && threadIdx.x == 0) g_flag = 0;

    const int I  = blockIdx.y;
    const int JB = blockIdx.x << 1;
    if (JB + 1 < I) return;            // fully lower-triangle: no-op

    __shared__ float4 As4[32][17];     // word stride 68
    __shared__ float4 Bs4[64][9];      // word stride 36
    __shared__ float2 redHi[4][32];

    const int tid = threadIdx.x;
    const int r   = tid >> 3;          // 0..31
    const int c8  = tid & 7;           // 0..7

    {   // A-strip: 2 cp.async per thread (coalesced 128B per 8-lane group)
        const float* arow = x + (size_t)(I * 32 + r) * D + JB * 32;
        #pragma unroll
        for (int jj = 0; jj < 2; jj++) {
            unsigned d = (unsigned)__cvta_generic_to_shared(&As4[r][jj * 8 + c8]);
            asm volatile("cp.async.cg.shared.global [%0], [%1], 16;"
                         :: "r"(d), "l"(arow + ((jj * 8 + c8) << 2)));
        }
    }
    #pragma unroll
    for (int jj = 0; jj < 2; jj++) {   // B-strip: 2 more
        const int rb = jj * 32 + r;
        unsigned d = (unsigned)__cvta_generic_to_shared(&Bs4[rb][c8]);
        asm volatile("cp.async.cg.shared.global [%0], [%1], 16;"
                     :: "r"(d), "l"(x + (size_t)(JB * 32 + rb) * D + I * 32 + (c8 << 2)));
    }
    asm volatile("cp.async.commit_group;");
    asm volatile("cp.async.wait_group 0;");
    __syncthreads();

    const int w = tid >> 5, l = tid & 31;
    const int c = w & 3, half = w >> 2;      // combo 0..3, half 0..1
    const int j = c >> 1, which = c & 1;
    const int J = JB + j;

    const float* Af = reinterpret_cast<const float*>(As4);
    const float* Bf = reinterpret_cast<const float*>(Bs4);

    float sm = 0.0f, sr = 0.0f;
    if (which == 0) {
        // column l of pair j, rows u = 16*half .. +15
        const int acol = (j << 5) + l;
        const float4* brow = Bs4[(j << 5) + l] + (half << 2);  // LDS.128, c-free
        #pragma unroll
        for (int q = 0; q < 4; q++) {
            const float4 b = brow[q];
            const int u = (((half << 2) + q) << 2);
            sm += Af[(u + 0) * 68 + acol] * b.x + Af[(u + 1) * 68 + acol] * b.y
                + Af[(u + 2) * 68 + acol] * b.z + Af[(u + 3) * 68 + acol] * b.w;
            sr += (b.x + b.y) + (b.z + b.w);
        }
    } else {
        // row l of pair j, cols v = 16*half .. +15
        const float4* arow4 = As4[l] + (j << 3) + (half << 2);  // LDS.128, c-free
        #pragma unroll
        for (int q = 0; q < 4; q++) {
            const float4 a = arow4[q];
            const int v = (j << 5) + (((half << 2) + q) << 2);
            sm += a.x * Bf[(v + 0) * 36 + l] + a.y * Bf[(v + 1) * 36 + l]
                + a.z * Bf[(v + 2) * 36 + l] + a.w * Bf[(v + 3) * 36 + l];
            sr += (a.x + a.y) + (a.z + a.w);
        }
    }
    if (half) redHi[c][l] = make_float2(sm, sr);
    __syncthreads();
    if (!half) {
        const float2 h = redHi[c][l];
        sm += h.x; sr += h.y;
        if (which == 0) {
            if (J >= I) { g_partM[I][J * 32 + l] = sm; g_partR[I][J * 32 + l] = sr; }
        } else {
            if (J > I)  { g_partM[J][I * 32 + l] = sm; g_partR[J][I * 32 + l] = sr; }
        }
    }
}

// ---------------------------------------------------------------------------
// Kernel 2 (fused, D==2048): 64 reducer blocks + 1024 consumer blocks.
// Reducers: reduce g_partM over p -> g_m (pre-scaled), threadfence, count flag.
// Consumers (2 rows each): batch k/x loads -> own-row rm reduce from g_partR ->
// nk compute+store (overlaps reducer latency) -> spin on flag -> y compute+store.
// ---------------------------------------------------------------------------
template<bool NK>
__global__ void __launch_bounds__(256) hebb_ew_fused(
    const float* __restrict__ x, const float* __restrict__ kmat,
    float* __restrict__ y, float* __restrict__ nk, float invD)
{
    const int bid  = blockIdx.x;
    const int tid  = threadIdx.x;
    const int lane = tid & 31, w = tid >> 5;

    if (bid < 64) {
        // m-reducer: 32 columns per block.
        __shared__ float sM[8][33];
        const int jcol = (bid << 5) + lane;
        float s = 0.0f;
        #pragma unroll 8
        for (int p = w; p < NTMAX; p += 8) s += g_partM[p][jcol];
        sM[w][lane] = s;
        __syncthreads();
        if (tid < 32) {
            float m = 0.0f;
            #pragma unroll
            for (int k = 0; k < 8; k++) m += sM[k][tid];
            g_m[(bid << 5) + tid] = m * invD;
            __threadfence();           // publish before counting
        }
        __syncthreads();
        if (tid == 0) atomicAdd(&g_flag, 1u);
        return;
    }

    const int cid = bid - 64;          // 0..1023
    const int row = cid << 1;
    const size_t b0 = (size_t)row << 9;    // row * 512 float4
    const size_t b1 = b0 + 512;
    const int c0 = tid, c1 = tid + 256;

    const float4* k0 = reinterpret_cast<const float4*>(kmat) + b0;
    const float4* k1 = reinterpret_cast<const float4*>(kmat) + b1;
    const float4* x0 = reinterpret_cast<const float4*>(x) + b0;
    const float4* x1 = reinterpret_cast<const float4*>(x) + b1;

    // Front-batched DRAM loads.
    float4 ka0 = k0[c0], kb0 = k0[c1], ka1 = k1[c0], kb1 = k1[c1];
    float4 xa0, xb0, xa1, xb1;
    if (NK) { xa0 = x0[c0]; xb0 = x0[c1]; xa1 = x1[c0]; xb1 = x1[c1]; }

    // Own-row rm reduce (L2, overlaps the DRAM loads above).
    __shared__ float srm[2];
    if (w < 2) {
        const int rr = row + w;
        float s = g_partR[lane][rr] + g_partR[lane + 32][rr];
        #pragma unroll
        for (int o = 16; o > 0; o >>= 1) s += __shfl_xor_sync(0xFFFFFFFFu, s, o);
        if (lane == 0) srm[w] = s * (invD * ETA);
    }
    __syncthreads();
    const float rm0 = srm[0], rm1 = srm[1];

    if (NK) {
        float4* n0 = reinterpret_cast<float4*>(nk) + b0;
        float4* n1 = reinterpret_cast<float4*>(nk) + b1;
        float4 v;
        v.x = fmaf(rm0, xa0.x, ka0.x); v.y = fmaf(rm0, xa0.y, ka0.y);
        v.z = fmaf(rm0, xa0.z, ka0.z); v.w = fmaf(rm0, xa0.w, ka0.w);
        n0[c0] = v;
        v.x = fmaf(rm0, xb0.x, kb0.x); v.y = fmaf(rm0, xb0.y, kb0.y);
        v.z = fmaf(rm0, xb0.z, kb0.z); v.w = fmaf(rm0, xb0.w, kb0.w);
        n0[c1] = v;
        v.x = fmaf(rm1, xa1.x, ka1.x); v.y = fmaf(rm1, xa1.y, ka1.y);
        v.z = fmaf(rm1, xa1.z, ka1.z); v.w = fmaf(rm1, xa1.w, ka1.w);
        n1[c0] = v;
        v.x = fmaf(rm1, xb1.x, kb1.x); v.y = fmaf(rm1, xb1.y, kb1.y);
        v.z = fmaf(rm1, xb1.z, kb1.z); v.w = fmaf(rm1, xb1.w, kb1.w);
        n1[c1] = v;
    }

    // Wait for the in-grid reducers (bids 0..63, scheduled in wave 1).
    if (tid == 0) {
        volatile unsigned int* f = &g_flag;
        while (*f < 64u) { __nanosleep(64); }
        __threadfence();
    }
    __syncthreads();

    const float4* m4 = reinterpret_cast<const float4*>(g_m);
    const float4 ma = m4[c0], mb = m4[c1];
    float4* y0 = reinterpret_cast<float4*>(y) + b0;
    float4* y1 = reinterpret_cast<float4*>(y) + b1;
    float4 v;
    v.x = ka0.x * ma.x; v.y = ka0.y * ma.y; v.z = ka0.z * ma.z; v.w = ka0.w * ma.w;
    y0[c0] = v;
    v.x = kb0.x * mb.x; v.y = kb0.y * mb.y; v.z = kb0.z * mb.z; v.w = kb0.w * mb.w;
    y0[c1] = v;
    v.x = ka1.x * ma.x; v.y = ka1.y * ma.y; v.z = ka1.z * ma.z; v.w = ka1.w * ma.w;
    y1[c0] = v;
    v.x = kb1.x * mb.x; v.y = kb1.y * mb.y; v.z = kb1.z * mb.z; v.w = kb1.w * mb.w;
    y1[c1] = v;
}

// ------------------- generic fallback path (non-2048 D) --------------------
__global__ void __launch_bounds__(256) hebb_reduce_kernel(int NT, float invD)
{
    __shared__ float sM[8][33];
    __shared__ float sR[8][33];
    const int lane = threadIdx.x & 31;
    const int g    = threadIdx.x >> 5;
    const int j    = blockIdx.x * 32 + lane;
    float sm = 0.0f, sr = 0.0f;
    for (int p = g; p < NT; p += 8) { sm += g_partM[p][j]; sr += g_partR[p][j]; }
    sM[g][lane] = sm; sR[g][lane] = sr;
    __syncthreads();
    if (threadIdx.x < 32) {
        float m = 0.0f, r = 0.0f;
        #pragma unroll
        for (int k = 0; k < 8; k++) { m += sM[k][threadIdx.x]; r += sR[k][threadIdx.x]; }
        const int jj = blockIdx.x * 32 + threadIdx.x;
        g_m[jj]  = m * invD;
        g_rm[jj] = r * (invD * ETA);
    }
}

__global__ void __launch_bounds__(256) hebb_ew_kernel_g(
    const float* __restrict__ x, const float* __restrict__ kmat,
    float* __restrict__ y, float* __restrict__ nk, int D4, int n4, int write_nk)
{
    int idx = blockIdx.x * 256 + threadIdx.x;
    if (idx >= n4) return;
    const int col4 = idx % D4;
    const int row  = idx / D4;
    float4 kv = reinterpret_cast<const float4*>(kmat)[idx];
    float4 mv = reinterpret_cast<const float4*>(g_m)[col4];
    float4 yv;
    yv.x = kv.x * mv.x; yv.y = kv.y * mv.y; yv.z = kv.z * mv.z; yv.w = kv.w * mv.w;
    reinterpret_cast<float4*>(y)[idx] = yv;
    if (write_nk) {
        float rm = g_rm[row];
        float4 xv = reinterpret_cast<const float4*>(x)[idx];
        float4 nv;
        nv.x = fmaf(rm, xv.x, kv.x); nv.y = fmaf(rm, xv.y, kv.y);
        nv.z = fmaf(rm, xv.z, kv.z); nv.w = fmaf(rm, xv.w, kv.w);
        reinterpret_cast<float4*>(nk)[idx] = nv;
    }
}

extern "C" void kernel_launch(void* const* d_in, const int* in_sizes, int n_in,
                              void* d_out, int out_size)
{
    if (n_in < 2 || !d_in || !d_out || !in_sizes) return;

    const float* x    = (const float*)d_in[0];
    const float* kmat = (const float*)d_in[1];
    float* out        = (float*)d_out;

    const int n = in_sizes[0];           // D*D
    int D = 1;
    while (D < MAXD && D * D < n) D++;   // D = 2048 here
    if (D * D != n || (D % 64) != 0) return;

    const int NT = D / 32;
    const int write_nk = (out_size >= 2 * n) ? 1 : 0;
    const float invD = 1.0f / (float)D;

    float* y  = out;
    float* nk = out + n;

    dim3 tgrid(NT / 2, NT);              // (32, 64) for D=2048
    hebb_tile_kernel<<<tgrid, 256>>>(x, D);

    if (D == 2048) {
        if (write_nk)
            hebb_ew_fused<true><<<64 + 1024, 256>>>(x, kmat, y, nk, invD);
        else
            hebb_ew_fused<false><<<64 + 1024, 256>>>(x, kmat, y, nk, invD);
    } else {
        hebb_reduce_kernel<<<D / 32, 256>>>(NT, invD);
        const int n4 = n >> 2;
        hebb_ew_kernel_g<<<(n4 + 255) / 256, 256>>>(x, kmat, y, nk, D >> 2, n4, write_nk);
    }
}

// round 16
// speedup vs baseline: 1.1139x; 1.0521x over previous
#include <cuda_runtime.h>

#define MAXD 2048
#define NTMAX 64
#define ETA 0.005f

// Disjoint partials; every slot written exactly once per launch.
__device__ float g_partM[NTMAX][MAXD];   // 512 KB
__device__ float g_partR[NTMAX][MAXD];   // 512 KB
__device__ float g_m[MAXD];              // m[j]  (pre-scaled by 1/D)
__device__ float g_rm[MAXD];             // rowmean[b] * ETA / D

// ---------------------------------------------------------------------------
// Kernel 1 (UNCHANGED from r15 — measured ~1.8us): symmetric strip-pair
// reduction. 2-tile strips (18 KB smem -> ~8 blocks/SM), cp.async loads.
// Block (I, JB=2bx): A-strip = x[I, JB..JB+1] (32x64), B-strip (64x32).
// 8 warps: combo c = (pair j, pass) x half; halves combined via shared.
// ---------------------------------------------------------------------------
__global__ void __launch_bounds__(256) hebb_tile_kernel(
    const float* __restrict__ x, int D)
{
    const int I  = blockIdx.y;
    const int JB = blockIdx.x << 1;
    if (JB + 1 < I) return;            // fully lower-triangle: no-op

    __shared__ float4 As4[32][17];     // word stride 68
    __shared__ float4 Bs4[64][9];      // word stride 36
    __shared__ float2 redHi[4][32];

    const int tid = threadIdx.x;
    const int r   = tid >> 3;          // 0..31
    const int c8  = tid & 7;           // 0..7

    {   // A-strip: 2 cp.async per thread (coalesced 128B per 8-lane group)
        const float* arow = x + (size_t)(I * 32 + r) * D + JB * 32;
        #pragma unroll
        for (int jj = 0; jj < 2; jj++) {
            unsigned d = (unsigned)__cvta_generic_to_shared(&As4[r][jj * 8 + c8]);
            asm volatile("cp.async.cg.shared.global [%0], [%1], 16;"
                         :: "r"(d), "l"(arow + ((jj * 8 + c8) << 2)));
        }
    }
    #pragma unroll
    for (int jj = 0; jj < 2; jj++) {   // B-strip: 2 more
        const int rb = jj * 32 + r;
        unsigned d = (unsigned)__cvta_generic_to_shared(&Bs4[rb][c8]);
        asm volatile("cp.async.cg.shared.global [%0], [%1], 16;"
                     :: "r"(d), "l"(x + (size_t)(JB * 32 + rb) * D + I * 32 + (c8 << 2)));
    }
    asm volatile("cp.async.commit_group;");
    asm volatile("cp.async.wait_group 0;");
    __syncthreads();

    const int w = tid >> 5, l = tid & 31;
    const int c = w & 3, half = w >> 2;      // combo 0..3, half 0..1
    const int j = c >> 1, which = c & 1;
    const int J = JB + j;

    const float* Af = reinterpret_cast<const float*>(As4);
    const float* Bf = reinterpret_cast<const float*>(Bs4);

    float sm = 0.0f, sr = 0.0f;
    if (which == 0) {
        // column l of pair j, rows u = 16*half .. +15
        const int acol = (j << 5) + l;
        const float4* brow = Bs4[(j << 5) + l] + (half << 2);  // LDS.128, c-free
        #pragma unroll
        for (int q = 0; q < 4; q++) {
            const float4 b = brow[q];
            const int u = (((half << 2) + q) << 2);
            sm += Af[(u + 0) * 68 + acol] * b.x + Af[(u + 1) * 68 + acol] * b.y
                + Af[(u + 2) * 68 + acol] * b.z + Af[(u + 3) * 68 + acol] * b.w;
            sr += (b.x + b.y) + (b.z + b.w);
        }
    } else {
        // row l of pair j, cols v = 16*half .. +15
        const float4* arow4 = As4[l] + (j << 3) + (half << 2);  // LDS.128, c-free
        #pragma unroll
        for (int q = 0; q < 4; q++) {
            const float4 a = arow4[q];
            const int v = (j << 5) + (((half << 2) + q) << 2);
            sm += a.x * Bf[(v + 0) * 36 + l] + a.y * Bf[(v + 1) * 36 + l]
                + a.z * Bf[(v + 2) * 36 + l] + a.w * Bf[(v + 3) * 36 + l];
            sr += (a.x + a.y) + (a.z + a.w);
        }
    }
    if (half) redHi[c][l] = make_float2(sm, sr);
    __syncthreads();
    if (!half) {
        const float2 h = redHi[c][l];
        sm += h.x; sr += h.y;
        if (which == 0) {
            if (J >= I) { g_partM[I][J * 32 + l] = sm; g_partR[I][J * 32 + l] = sr; }
        } else {
            if (J > I)  { g_partM[J][I * 32 + l] = sm; g_partR[J][I * 32 + l] = sr; }
        }
    }
}

// ---------------------------------------------------------------------------
// Kernel 2: partials reduction (separate launch again; the in-grid fusion
// serialized consumers in r15). 64 blocks for D=2048, ~1 MB L2-hot.
// ---------------------------------------------------------------------------
__global__ void __launch_bounds__(256) hebb_reduce_kernel(int NT, float invD)
{
    __shared__ float sM[8][33];
    __shared__ float sR[8][33];
    const int lane = threadIdx.x & 31;
    const int g    = threadIdx.x >> 5;
    const int j    = blockIdx.x * 32 + lane;
    float sm = 0.0f, sr = 0.0f;
    for (int p = g; p < NT; p += 8) { sm += g_partM[p][j]; sr += g_partR[p][j]; }
    sM[g][lane] = sm; sR[g][lane] = sr;
    __syncthreads();
    if (threadIdx.x < 32) {
        float m = 0.0f, r = 0.0f;
        #pragma unroll
        for (int k = 0; k < 8; k++) { m += sM[k][threadIdx.x]; r += sR[k][threadIdx.x]; }
        const int jj = blockIdx.x * 32 + threadIdx.x;
        g_m[jj]  = m * invD;
        g_rm[jj] = r * (invD * ETA);
    }
}

// ---------------------------------------------------------------------------
// Kernel 3 (D==2048): elementwise outputs; r14 consumer structure WITHOUT the
// spin. 1024 blocks x 2 rows; 8 front-batched LDG.128 + broadcast rm loads.
//   y[i,j]  = kernel[i,j] * m[j]
//   nk[i,j] = kernel[i,j] + rm[i] * x[i,j]
// ---------------------------------------------------------------------------
template<bool NK>
__global__ void __launch_bounds__(256) hebb_ew_kernel_s(
    const float* __restrict__ x, const float* __restrict__ kmat,
    float* __restrict__ y, float* __restrict__ nk)
{
    const int tid = threadIdx.x;
    const int c0 = tid, c1 = tid + 256;
    const int row = blockIdx.x << 1;
    const size_t b0 = (size_t)row << 9;    // row * 512 float4
    const size_t b1 = b0 + 512;

    const float4* k0 = reinterpret_cast<const float4*>(kmat) + b0;
    const float4* k1 = reinterpret_cast<const float4*>(kmat) + b1;
    const float4* x0 = reinterpret_cast<const float4*>(x) + b0;
    const float4* x1 = reinterpret_cast<const float4*>(x) + b1;
    const float4* m4 = reinterpret_cast<const float4*>(g_m);

    // Front-batched loads (independent -> max MLP).
    float4 ka0 = k0[c0], kb0 = k0[c1], ka1 = k1[c0], kb1 = k1[c1];
    float4 ma = m4[c0], mb = m4[c1];
    float4 xa0, xb0, xa1, xb1;
    if (NK) { xa0 = x0[c0]; xb0 = x0[c1]; xa1 = x1[c0]; xb1 = x1[c1]; }
    const float rm0 = g_rm[row];
    const float rm1 = g_rm[row + 1];

    float4* y0 = reinterpret_cast<float4*>(y) + b0;
    float4* y1 = reinterpret_cast<float4*>(y) + b1;

    float4 v;
    v.x = ka0.x * ma.x; v.y = ka0.y * ma.y; v.z = ka0.z * ma.z; v.w = ka0.w * ma.w;
    y0[c0] = v;
    v.x = kb0.x * mb.x; v.y = kb0.y * mb.y; v.z = kb0.z * mb.z; v.w = kb0.w * mb.w;
    y0[c1] = v;
    v.x = ka1.x * ma.x; v.y = ka1.y * ma.y; v.z = ka1.z * ma.z; v.w = ka1.w * ma.w;
    y1[c0] = v;
    v.x = kb1.x * mb.x; v.y = kb1.y * mb.y; v.z = kb1.z * mb.z; v.w = kb1.w * mb.w;
    y1[c1] = v;

    if (NK) {
        float4* n0 = reinterpret_cast<float4*>(nk) + b0;
        float4* n1 = reinterpret_cast<float4*>(nk) + b1;
        v.x = fmaf(rm0, xa0.x, ka0.x); v.y = fmaf(rm0, xa0.y, ka0.y);
        v.z = fmaf(rm0, xa0.z, ka0.z); v.w = fmaf(rm0, xa0.w, ka0.w);
        n0[c0] = v;
        v.x = fmaf(rm0, xb0.x, kb0.x); v.y = fmaf(rm0, xb0.y, kb0.y);
        v.z = fmaf(rm0, xb0.z, kb0.z); v.w = fmaf(rm0, xb0.w, kb0.w);
        n0[c1] = v;
        v.x = fmaf(rm1, xa1.x, ka1.x); v.y = fmaf(rm1, xa1.y, ka1.y);
        v.z = fmaf(rm1, xa1.z, ka1.z); v.w = fmaf(rm1, xa1.w, ka1.w);
        n1[c0] = v;
        v.x = fmaf(rm1, xb1.x, kb1.x); v.y = fmaf(rm1, xb1.y, kb1.y);
        v.z = fmaf(rm1, xb1.z, kb1.z); v.w = fmaf(rm1, xb1.w, kb1.w);
        n1[c1] = v;
    }
}

// Generic fallback (runtime D4).
__global__ void __launch_bounds__(256) hebb_ew_kernel_g(
    const float* __restrict__ x, const float* __restrict__ kmat,
    float* __restrict__ y, float* __restrict__ nk, int D4, int n4, int write_nk)
{
    int idx = blockIdx.x * 256 + threadIdx.x;
    if (idx >= n4) return;
    const int col4 = idx % D4;
    const int row  = idx / D4;
    float4 kv = reinterpret_cast<const float4*>(kmat)[idx];
    float4 mv = reinterpret_cast<const float4*>(g_m)[col4];
    float4 yv;
    yv.x = kv.x * mv.x; yv.y = kv.y * mv.y; yv.z = kv.z * mv.z; yv.w = kv.w * mv.w;
    reinterpret_cast<float4*>(y)[idx] = yv;
    if (write_nk) {
        float rm = g_rm[row];
        float4 xv = reinterpret_cast<const float4*>(x)[idx];
        float4 nv;
        nv.x = fmaf(rm, xv.x, kv.x); nv.y = fmaf(rm, xv.y, kv.y);
        nv.z = fmaf(rm, xv.z, kv.z); nv.w = fmaf(rm, xv.w, kv.w);
        reinterpret_cast<float4*>(nk)[idx] = nv;
    }
}

extern "C" void kernel_launch(void* const* d_in, const int* in_sizes, int n_in,
                              void* d_out, int out_size)
{
    if (n_in < 2 || !d_in || !d_out || !in_sizes) return;

    const float* x    = (const float*)d_in[0];
    const float* kmat = (const float*)d_in[1];
    float* out        = (float*)d_out;

    const int n = in_sizes[0];           // D*D
    int D = 1;
    while (D < MAXD && D * D < n) D++;   // D = 2048 here
    if (D * D != n || (D % 64) != 0) return;

    const int NT = D / 32;
    const int write_nk = (out_size >= 2 * n) ? 1 : 0;
    const float invD = 1.0f / (float)D;

    float* y  = out;
    float* nk = out + n;

    dim3 tgrid(NT / 2, NT);              // (32, 64) for D=2048
    hebb_tile_kernel<<<tgrid, 256>>>(x, D);
    hebb_reduce_kernel<<<D / 32, 256>>>(NT, invD);

    if (D == 2048) {
        if (write_nk)
            hebb_ew_kernel_s<true><<<1024, 256>>>(x, kmat, y, nk);
        else
            hebb_ew_kernel_s<false><<<1024, 256>>>(x, kmat, y, nk);
    } else {
        const int n4 = n >> 2;
        hebb_ew_kernel_g<<<(n4 + 255) / 256, 256>>>(x, kmat, y, nk, D >> 2, n4, write_nk);
    }
}